// round 1
// baseline (speedup 1.0000x reference)
#include <cuda_runtime.h>
#include <math.h>

static constexpr int B_   = 4;
static constexpr int N_   = 4096;
static constexpr int H_   = 16;
static constexpr int DK_  = 128;
static constexpr int DIM_ = 2048;
static constexpr int BH_  = B_ * H_;      // 64
static constexpr int MROWS_ = B_ * N_;    // 16384
static constexpr float INV_SQRT_DK = 0.08838834764831843f;

// d_out layout: out (B*N*DIM), M_fast (B*H*DK*DV), M_slow, psi (B*H)
static constexpr long long OUT_OFF_MF  = 33554432LL;
static constexpr long long OUT_OFF_MS  = 34603008LL;
static constexpr long long OUT_OFF_PSI = 35651584LL;

// ---------------- scratch (allocation-free: device globals) ----------------
__device__ float g_q  [(size_t)BH_ * N_ * DK_];   // (b,h,n,d)
__device__ float g_kf [(size_t)BH_ * N_ * DK_];   // k raw, then k_fast in place
__device__ float g_ksl[(size_t)BH_ * N_ * DK_];   // k_slow
__device__ float g_v  [(size_t)BH_ * N_ * DK_];   // (b,h,n,v)
__device__ float g_o  [(size_t)MROWS_ * DIM_];    // (b,n,h,v)
__device__ float g_part[2LL * BH_ * 8 * DK_ * DK_];
__device__ float g_mblend[(size_t)BH_ * DK_ * DK_];
__device__ float g_meanpart[8 * B_ * DIM_];
__device__ float g_mean[B_ * DIM_];
__device__ float g_h1[B_ * 1024];

// ======================= mean over N =======================
__global__ void k_meanpart(const float* __restrict__ x) {
    int gid = blockIdx.x * 256 + threadIdx.x;        // 65536 threads
    int sp = gid >> 13;                               // 0..7
    int r  = gid & 8191;                              // b*2048 + d
    int b = r >> 11, d = r & 2047;
    float s = 0.f;
    int nbeg = sp * 512;
    #pragma unroll 4
    for (int n = nbeg; n < nbeg + 512; n++)
        s += x[(size_t)(b * N_ + n) * DIM_ + d];
    g_meanpart[gid] = s;
}

__global__ void k_meanred() {
    int r = blockIdx.x * 256 + threadIdx.x;           // 0..8191
    float s = 0.f;
    #pragma unroll
    for (int sp = 0; sp < 8; sp++) s += g_meanpart[sp * 8192 + r];
    g_mean[r] = s * (1.f / 4096.f);
}

// ======================= gating MLP =======================
__global__ void k_mlp1(const float* __restrict__ f1_w, const float* __restrict__ f1_b) {
    __shared__ float xm[2048];
    int b = blockIdx.x;
    for (int i = threadIdx.x; i < 2048; i += 256) xm[i] = g_mean[b * 2048 + i];
    __syncthreads();
    int j = blockIdx.y * 256 + threadIdx.x;           // 0..1023
    float s = 0.f;
    for (int k = 0; k < 2048; k++)
        s = fmaf(xm[k], f1_w[(size_t)k * 1024 + j], s);
    s += f1_b[j];
    g_h1[b * 1024 + j] = s / (1.f + expf(-s));        // silu
}

__global__ void k_mlp2(const float* __restrict__ f2_w, const float* __restrict__ f2_b,
                       float* __restrict__ dout) {
    __shared__ float red[128];
    int bh = blockIdx.x;
    int b = bh >> 4, h = bh & 15;
    float s = 0.f;
    for (int k = threadIdx.x; k < 1024; k += 128)
        s = fmaf(g_h1[b * 1024 + k], f2_w[k * 16 + h], s);
    red[threadIdx.x] = s; __syncthreads();
    for (int off = 64; off > 0; off >>= 1) {
        if (threadIdx.x < off) red[threadIdx.x] += red[threadIdx.x + off];
        __syncthreads();
    }
    if (threadIdx.x == 0) {
        float z = red[0] + f2_b[h];
        dout[OUT_OFF_PSI + bh] = 1.f / (1.f + expf(-z));
    }
}

// ======================= QKV projection GEMM =======================
// C(16384 x 6144) = X(16384x2048) @ [Wq|Wk|Wv]; epilogue scatters to (b,h,n,d)
__global__ __launch_bounds__(256, 2)
void k_qkv(const float* __restrict__ x, const float* __restrict__ Wq,
           const float* __restrict__ Wk, const float* __restrict__ Wv) {
    __shared__ float As[16][132];
    __shared__ float Bs[16][128];
    const int m0 = blockIdx.x * 128;
    const int j0 = blockIdx.y * 128;                  // 0..6143
    const int which = j0 >> 11;
    const float* __restrict__ W = (which == 0) ? Wq : (which == 1 ? Wk : Wv);
    const int jj0 = j0 & 2047;
    const int tx = threadIdx.x, ty = threadIdx.y;
    const int tid = ty * 16 + tx;
    float acc[8][8];
    #pragma unroll
    for (int i = 0; i < 8; i++)
        #pragma unroll
        for (int j = 0; j < 8; j++) acc[i][j] = 0.f;

    const int arow = tid >> 2, acol = (tid & 3) * 4;
    const int brow = tid >> 5, bcol = (tid & 31) * 4;

    for (int kt = 0; kt < 2048; kt += 16) {
        #pragma unroll
        for (int r = 0; r < 2; r++) {
            int row = arow + r * 64;
            float4 av = *(const float4*)&x[(size_t)(m0 + row) * 2048 + kt + acol];
            As[acol + 0][row] = av.x; As[acol + 1][row] = av.y;
            As[acol + 2][row] = av.z; As[acol + 3][row] = av.w;
        }
        #pragma unroll
        for (int r = 0; r < 2; r++) {
            int row = brow + r * 8;
            *(float4*)&Bs[row][bcol] =
                *(const float4*)&W[(size_t)(kt + row) * 2048 + jj0 + bcol];
        }
        __syncthreads();
        #pragma unroll
        for (int kk = 0; kk < 16; kk++) {
            float a[8], bb[8];
            *(float4*)&a[0]  = *(const float4*)&As[kk][ty * 8];
            *(float4*)&a[4]  = *(const float4*)&As[kk][ty * 8 + 4];
            *(float4*)&bb[0] = *(const float4*)&Bs[kk][tx * 8];
            *(float4*)&bb[4] = *(const float4*)&Bs[kk][tx * 8 + 4];
            #pragma unroll
            for (int i = 0; i < 8; i++)
                #pragma unroll
                for (int j = 0; j < 8; j++)
                    acc[i][j] = fmaf(a[i], bb[j], acc[i][j]);
        }
        __syncthreads();
    }
    float* dst = (which == 0) ? g_q : (which == 1 ? g_kf : g_v);
    const int h = jj0 >> 7;         // constant per block
    const int b = m0 >> 12;         // constant per block
    const int n0 = m0 & 4095;
    const size_t base = (size_t)(b * H_ + h) * N_ * DK_;
    #pragma unroll
    for (int i = 0; i < 8; i++) {
        int n = n0 + ty * 8 + i;
        #pragma unroll
        for (int j = 0; j < 8; j += 4) {
            float4 v4 = make_float4(acc[i][j], acc[i][j+1], acc[i][j+2], acc[i][j+3]);
            *(float4*)&dst[base + (size_t)n * DK_ + tx * 8 + j] = v4;
        }
    }
}

// ======================= resonance + k_mod + decay split =======================
// per (b,h): res = k @ Wb[h]; k_fast/k_slow written (k_fast in place over g_kf)
__global__ __launch_bounds__(256, 2)
void k_res(const float* __restrict__ Wb, const float* __restrict__ fast_slope,
           const float* __restrict__ slow_slope) {
    __shared__ float As[16][132];
    __shared__ float Bs[16][128];
    const int m0 = blockIdx.x * 128;                  // n within slab
    const int bh = blockIdx.y;
    const int h = bh & 15;
    float* __restrict__ kslab = g_kf + (size_t)bh * N_ * DK_;
    float* __restrict__ kslow = g_ksl + (size_t)bh * N_ * DK_;
    const float* __restrict__ Wbh = Wb + (size_t)h * DK_ * DK_;
    const int tx = threadIdx.x, ty = threadIdx.y;
    const int tid = ty * 16 + tx;
    float acc[8][8];
    #pragma unroll
    for (int i = 0; i < 8; i++)
        #pragma unroll
        for (int j = 0; j < 8; j++) acc[i][j] = 0.f;

    const int arow = tid >> 2, acol = (tid & 3) * 4;
    const int brow = tid >> 5, bcol = (tid & 31) * 4;

    for (int kt = 0; kt < 128; kt += 16) {
        #pragma unroll
        for (int r = 0; r < 2; r++) {
            int row = arow + r * 64;
            float4 av = *(const float4*)&kslab[(size_t)(m0 + row) * DK_ + kt + acol];
            As[acol + 0][row] = av.x; As[acol + 1][row] = av.y;
            As[acol + 2][row] = av.z; As[acol + 3][row] = av.w;
        }
        #pragma unroll
        for (int r = 0; r < 2; r++) {
            int row = brow + r * 8;
            *(float4*)&Bs[row][bcol] =
                *(const float4*)&Wbh[(size_t)(kt + row) * DK_ + bcol];
        }
        __syncthreads();
        #pragma unroll
        for (int kk = 0; kk < 16; kk++) {
            float a[8], bb[8];
            *(float4*)&a[0]  = *(const float4*)&As[kk][ty * 8];
            *(float4*)&a[4]  = *(const float4*)&As[kk][ty * 8 + 4];
            *(float4*)&bb[0] = *(const float4*)&Bs[kk][tx * 8];
            *(float4*)&bb[4] = *(const float4*)&Bs[kk][tx * 8 + 4];
            #pragma unroll
            for (int i = 0; i < 8; i++)
                #pragma unroll
                for (int j = 0; j < 8; j++)
                    acc[i][j] = fmaf(a[i], bb[j], acc[i][j]);
        }
        __syncthreads();
    }
    const float fs = fast_slope[h], ss = slow_slope[h];
    #pragma unroll
    for (int i = 0; i < 8; i++) {
        int n = m0 + ty * 8 + i;
        float idx = (float)(n - (N_ - 1));
        float fw = expf(fs * idx);
        float sw = expf(ss * idx);
        #pragma unroll
        for (int j = 0; j < 8; j += 4) {
            size_t p = (size_t)n * DK_ + tx * 8 + j;
            float4 kr = *(const float4*)&kslab[p];
            float4 kf4, ks4;
            float r0, km;
            r0 = tanhf(acc[i][j+0]); km = kr.x * (1.f + 0.5f * r0) * INV_SQRT_DK; kf4.x = km * fw; ks4.x = km * sw;
            r0 = tanhf(acc[i][j+1]); km = kr.y * (1.f + 0.5f * r0) * INV_SQRT_DK; kf4.y = km * fw; ks4.y = km * sw;
            r0 = tanhf(acc[i][j+2]); km = kr.z * (1.f + 0.5f * r0) * INV_SQRT_DK; kf4.z = km * fw; ks4.z = km * sw;
            r0 = tanhf(acc[i][j+3]); km = kr.w * (1.f + 0.5f * r0) * INV_SQRT_DK; kf4.w = km * fw; ks4.w = km * sw;
            *(float4*)&kslab[p] = kf4;
            *(float4*)&kslow[p] = ks4;
        }
    }
}

// ======================= M = k^T @ v partials (split-K over n) =======================
__global__ __launch_bounds__(256, 2)
void k_mpart() {
    __shared__ float As[16][128];
    __shared__ float Bs[16][128];
    const int split = blockIdx.x;                     // 0..7
    const int bh = blockIdx.y;
    const int which = blockIdx.z;                     // 0 fast, 1 slow
    const float* __restrict__ kslab =
        (which ? g_ksl : g_kf) + (size_t)bh * N_ * DK_ + (size_t)split * 512 * DK_;
    const float* __restrict__ vslab =
        g_v + (size_t)bh * N_ * DK_ + (size_t)split * 512 * DK_;
    const int tx = threadIdx.x, ty = threadIdx.y;
    const int tid = ty * 16 + tx;
    float acc[8][8];
    #pragma unroll
    for (int i = 0; i < 8; i++)
        #pragma unroll
        for (int j = 0; j < 8; j++) acc[i][j] = 0.f;

    const int lrow = tid >> 5, lcol = (tid & 31) * 4;

    for (int nt = 0; nt < 512; nt += 16) {
        #pragma unroll
        for (int r = 0; r < 2; r++) {
            int row = lrow + r * 8;
            *(float4*)&As[row][lcol] = *(const float4*)&kslab[(size_t)(nt + row) * DK_ + lcol];
            *(float4*)&Bs[row][lcol] = *(const float4*)&vslab[(size_t)(nt + row) * DK_ + lcol];
        }
        __syncthreads();
        #pragma unroll
        for (int kk = 0; kk < 16; kk++) {
            float a[8], bb[8];
            *(float4*)&a[0]  = *(const float4*)&As[kk][ty * 8];
            *(float4*)&a[4]  = *(const float4*)&As[kk][ty * 8 + 4];
            *(float4*)&bb[0] = *(const float4*)&Bs[kk][tx * 8];
            *(float4*)&bb[4] = *(const float4*)&Bs[kk][tx * 8 + 4];
            #pragma unroll
            for (int i = 0; i < 8; i++)
                #pragma unroll
                for (int j = 0; j < 8; j++)
                    acc[i][j] = fmaf(a[i], bb[j], acc[i][j]);
        }
        __syncthreads();
    }
    float* dst = g_part + (((size_t)which * BH_ + bh) * 8 + split) * 16384;
    #pragma unroll
    for (int i = 0; i < 8; i++)
        #pragma unroll
        for (int j = 0; j < 8; j += 4) {
            float4 v4 = make_float4(acc[i][j], acc[i][j+1], acc[i][j+2], acc[i][j+3]);
            *(float4*)&dst[(ty * 8 + i) * 128 + tx * 8 + j] = v4;
        }
}

// ======================= M finalize: sum partials + inter*prev -> d_out =======================
__global__ void k_mfin(const float* __restrict__ Mf_prev, const float* __restrict__ Ms_prev,
                       const float* __restrict__ inter_fast, const float* __restrict__ inter_slow,
                       float* __restrict__ dout) {
    const int bh = blockIdx.x;
    const int which = blockIdx.y;
    const int h = bh & 15;
    const float inter = which ? inter_slow[h] : inter_fast[h];
    const float* prev = (which ? Ms_prev : Mf_prev) + (size_t)bh * 16384;
    const float* part = g_part + ((size_t)which * BH_ + bh) * 8 * 16384;
    float* dst = dout + (which ? OUT_OFF_MS : OUT_OFF_MF) + (size_t)bh * 16384;
    for (int e = threadIdx.x; e < 16384; e += 256) {
        float s = 0.f;
        #pragma unroll
        for (int sp = 0; sp < 8; sp++) s += part[(size_t)sp * 16384 + e];
        dst[e] = prev[e] * inter + s;
    }
}

// ======================= Mref = (I+S) @ M, blended into g_mblend =======================
__global__ __launch_bounds__(256, 2)
void k_mref(const float* __restrict__ S_fast, const float* __restrict__ S_slow,
            const float* __restrict__ dout, int which) {
    __shared__ float As[16][132];
    __shared__ float Bs[16][128];
    const int bh = blockIdx.x;
    const int h = bh & 15;
    const float* __restrict__ S = (which ? S_slow : S_fast) + (size_t)h * 16384;
    const float* __restrict__ M = dout + (which ? OUT_OFF_MS : OUT_OFF_MF) + (size_t)bh * 16384;
    const int tx = threadIdx.x, ty = threadIdx.y;
    const int tid = ty * 16 + tx;
    float acc[8][8];
    #pragma unroll
    for (int i = 0; i < 8; i++)
        #pragma unroll
        for (int j = 0; j < 8; j++) acc[i][j] = 0.f;

    const int arow = tid >> 2, acol = (tid & 3) * 4;
    const int brow = tid >> 5, bcol = (tid & 31) * 4;

    for (int kt = 0; kt < 128; kt += 16) {
        #pragma unroll
        for (int r = 0; r < 2; r++) {
            int row = arow + r * 64;                  // d
            float4 av = *(const float4*)&S[(size_t)row * 128 + kt + acol];
            As[acol + 0][row] = av.x + ((row == kt + acol + 0) ? 1.f : 0.f);
            As[acol + 1][row] = av.y + ((row == kt + acol + 1) ? 1.f : 0.f);
            As[acol + 2][row] = av.z + ((row == kt + acol + 2) ? 1.f : 0.f);
            As[acol + 3][row] = av.w + ((row == kt + acol + 3) ? 1.f : 0.f);
        }
        #pragma unroll
        for (int r = 0; r < 2; r++) {
            int row = brow + r * 8;
            *(float4*)&Bs[row][bcol] = *(const float4*)&M[(size_t)(kt + row) * 128 + bcol];
        }
        __syncthreads();
        #pragma unroll
        for (int kk = 0; kk < 16; kk++) {
            float a[8], bb[8];
            *(float4*)&a[0]  = *(const float4*)&As[kk][ty * 8];
            *(float4*)&a[4]  = *(const float4*)&As[kk][ty * 8 + 4];
            *(float4*)&bb[0] = *(const float4*)&Bs[kk][tx * 8];
            *(float4*)&bb[4] = *(const float4*)&Bs[kk][tx * 8 + 4];
            #pragma unroll
            for (int i = 0; i < 8; i++)
                #pragma unroll
                for (int j = 0; j < 8; j++)
                    acc[i][j] = fmaf(a[i], bb[j], acc[i][j]);
        }
        __syncthreads();
    }
    const float p = dout[OUT_OFF_PSI + bh];
    const float c0 = which ? p : (1.f - p);
    float* dst = g_mblend + (size_t)bh * 16384;
    #pragma unroll
    for (int i = 0; i < 8; i++)
        #pragma unroll
        for (int j = 0; j < 8; j++) {
            int idx = (ty * 8 + i) * 128 + tx * 8 + j;
            if (which == 0) dst[idx] = c0 * acc[i][j];
            else            dst[idx] += c0 * acc[i][j];
        }
}

// ======================= o_blend = q @ M_blend, written (b,n,h,v) =======================
__global__ __launch_bounds__(256, 2)
void k_oblend() {
    __shared__ float As[16][132];
    __shared__ float Bs[16][128];
    const int m0 = blockIdx.x * 128;
    const int bh = blockIdx.y;
    const float* __restrict__ qslab = g_q + (size_t)bh * N_ * DK_;
    const float* __restrict__ Mb = g_mblend + (size_t)bh * 16384;
    const int tx = threadIdx.x, ty = threadIdx.y;
    const int tid = ty * 16 + tx;
    float acc[8][8];
    #pragma unroll
    for (int i = 0; i < 8; i++)
        #pragma unroll
        for (int j = 0; j < 8; j++) acc[i][j] = 0.f;

    const int arow = tid >> 2, acol = (tid & 3) * 4;
    const int brow = tid >> 5, bcol = (tid & 31) * 4;

    for (int kt = 0; kt < 128; kt += 16) {
        #pragma unroll
        for (int r = 0; r < 2; r++) {
            int row = arow + r * 64;
            float4 av = *(const float4*)&qslab[(size_t)(m0 + row) * DK_ + kt + acol];
            As[acol + 0][row] = av.x; As[acol + 1][row] = av.y;
            As[acol + 2][row] = av.z; As[acol + 3][row] = av.w;
        }
        #pragma unroll
        for (int r = 0; r < 2; r++) {
            int row = brow + r * 8;
            *(float4*)&Bs[row][bcol] = *(const float4*)&Mb[(size_t)(kt + row) * 128 + bcol];
        }
        __syncthreads();
        #pragma unroll
        for (int kk = 0; kk < 16; kk++) {
            float a[8], bb[8];
            *(float4*)&a[0]  = *(const float4*)&As[kk][ty * 8];
            *(float4*)&a[4]  = *(const float4*)&As[kk][ty * 8 + 4];
            *(float4*)&bb[0] = *(const float4*)&Bs[kk][tx * 8];
            *(float4*)&bb[4] = *(const float4*)&Bs[kk][tx * 8 + 4];
            #pragma unroll
            for (int i = 0; i < 8; i++)
                #pragma unroll
                for (int j = 0; j < 8; j++)
                    acc[i][j] = fmaf(a[i], bb[j], acc[i][j]);
        }
        __syncthreads();
    }
    const int b = bh >> 4, h = bh & 15;
    #pragma unroll
    for (int i = 0; i < 8; i++) {
        int n = m0 + ty * 8 + i;
        size_t base = ((size_t)(b * N_ + n) * H_ + h) * DK_;
        #pragma unroll
        for (int j = 0; j < 8; j += 4) {
            float4 v4 = make_float4(acc[i][j], acc[i][j+1], acc[i][j+2], acc[i][j+3]);
            *(float4*)&g_o[base + tx * 8 + j] = v4;
        }
    }
}

// ======================= output projection =======================
__global__ __launch_bounds__(256, 2)
void k_out(const float* __restrict__ Wo, float* __restrict__ dout) {
    __shared__ float As[16][132];
    __shared__ float Bs[16][128];
    const int m0 = blockIdx.x * 128;
    const int j0 = blockIdx.y * 128;
    const int tx = threadIdx.x, ty = threadIdx.y;
    const int tid = ty * 16 + tx;
    float acc[8][8];
    #pragma unroll
    for (int i = 0; i < 8; i++)
        #pragma unroll
        for (int j = 0; j < 8; j++) acc[i][j] = 0.f;

    const int arow = tid >> 2, acol = (tid & 3) * 4;
    const int brow = tid >> 5, bcol = (tid & 31) * 4;

    for (int kt = 0; kt < 2048; kt += 16) {
        #pragma unroll
        for (int r = 0; r < 2; r++) {
            int row = arow + r * 64;
            float4 av = *(const float4*)&g_o[(size_t)(m0 + row) * 2048 + kt + acol];
            As[acol + 0][row] = av.x; As[acol + 1][row] = av.y;
            As[acol + 2][row] = av.z; As[acol + 3][row] = av.w;
        }
        #pragma unroll
        for (int r = 0; r < 2; r++) {
            int row = brow + r * 8;
            *(float4*)&Bs[row][bcol] =
                *(const float4*)&Wo[(size_t)(kt + row) * 2048 + j0 + bcol];
        }
        __syncthreads();
        #pragma unroll
        for (int kk = 0; kk < 16; kk++) {
            float a[8], bb[8];
            *(float4*)&a[0]  = *(const float4*)&As[kk][ty * 8];
            *(float4*)&a[4]  = *(const float4*)&As[kk][ty * 8 + 4];
            *(float4*)&bb[0] = *(const float4*)&Bs[kk][tx * 8];
            *(float4*)&bb[4] = *(const float4*)&Bs[kk][tx * 8 + 4];
            #pragma unroll
            for (int i = 0; i < 8; i++)
                #pragma unroll
                for (int j = 0; j < 8; j++)
                    acc[i][j] = fmaf(a[i], bb[j], acc[i][j]);
        }
        __syncthreads();
    }
    #pragma unroll
    for (int i = 0; i < 8; i++) {
        size_t base = (size_t)(m0 + ty * 8 + i) * 2048 + j0;
        #pragma unroll
        for (int j = 0; j < 8; j += 4) {
            float4 v4 = make_float4(acc[i][j], acc[i][j+1], acc[i][j+2], acc[i][j+3]);
            *(float4*)&dout[base + tx * 8 + j] = v4;
        }
    }
}

// ======================= launch =======================
extern "C" void kernel_launch(void* const* d_in, const int* in_sizes, int n_in,
                              void* d_out, int out_size) {
    (void)in_sizes; (void)n_in; (void)out_size;
    const float* x          = (const float*)d_in[0];
    const float* Mf_prev    = (const float*)d_in[1];
    const float* Ms_prev    = (const float*)d_in[2];
    const float* Wq         = (const float*)d_in[3];
    const float* Wk         = (const float*)d_in[4];
    const float* Wv         = (const float*)d_in[5];
    const float* Wo         = (const float*)d_in[6];
    const float* Wb         = (const float*)d_in[7];
    const float* fast_slope = (const float*)d_in[8];
    const float* slow_slope = (const float*)d_in[9];
    const float* inter_fast = (const float*)d_in[10];
    const float* inter_slow = (const float*)d_in[11];
    const float* S_fast     = (const float*)d_in[12];
    const float* S_slow     = (const float*)d_in[13];
    const float* f1_w       = (const float*)d_in[14];
    const float* f1_b       = (const float*)d_in[15];
    const float* f2_w       = (const float*)d_in[16];
    const float* f2_b       = (const float*)d_in[17];
    float* out = (float*)d_out;

    dim3 t16(16, 16);

    // gating path (independent of QKV)
    k_meanpart<<<256, 256>>>(x);
    k_meanred<<<32, 256>>>();
    k_mlp1<<<dim3(4, 4), 256>>>(f1_w, f1_b);
    k_mlp2<<<64, 128>>>(f2_w, f2_b, out);

    // main path
    k_qkv<<<dim3(128, 48), t16>>>(x, Wq, Wk, Wv);
    k_res<<<dim3(32, 64), t16>>>(Wb, fast_slope, slow_slope);
    k_mpart<<<dim3(8, 64, 2), t16>>>();
    k_mfin<<<dim3(64, 2), 256>>>(Mf_prev, Ms_prev, inter_fast, inter_slow, out);
    k_mref<<<64, t16>>>(S_fast, S_slow, out, 0);
    k_mref<<<64, t16>>>(S_fast, S_slow, out, 1);
    k_oblend<<<dim3(32, 64), t16>>>();
    k_out<<<dim3(128, 16), t16>>>(Wo, out);
}

// round 5
// speedup vs baseline: 1.7166x; 1.7166x over previous
#include <cuda_runtime.h>
#include <cuda_bf16.h>
#include <cstdint>
#include <math.h>

static constexpr int B_   = 4;
static constexpr int N_   = 4096;
static constexpr int H_   = 16;
static constexpr int DK_  = 128;
static constexpr int DIM_ = 2048;
static constexpr int BH_  = B_ * H_;      // 64
static constexpr int MROWS_ = B_ * N_;    // 16384
static constexpr float INV_SQRT_DK = 0.08838834764831843f;

static constexpr long long OUT_OFF_MF  = 33554432LL;
static constexpr long long OUT_OFF_MS  = 34603008LL;
static constexpr long long OUT_OFF_PSI = 35651584LL;

// ---------------- scratch (allocation-free: device globals) ----------------
__device__ float g_q  [(size_t)BH_ * N_ * DK_];   // (b,h,n,d) fp32
__device__ float g_kf [(size_t)BH_ * N_ * DK_];   // k raw -> k_fast in place
__device__ float g_ksl[(size_t)BH_ * N_ * DK_];   // k_slow
__device__ float g_v  [(size_t)BH_ * N_ * DK_];   // (b,h,n,v) fp32
__device__ float g_part[2LL * BH_ * 8 * DK_ * DK_];
__device__ float g_mblend[(size_t)BH_ * DK_ * DK_];
__device__ float g_meanpart[8 * B_ * DIM_];
__device__ float g_mean[B_ * DIM_];
__device__ float g_h1[B_ * 1024];

// bf16 split operands for HMMA GEMMs
__device__ __nv_bfloat16 g_xh [(size_t)MROWS_ * DIM_];   // x hi  [16384][2048]
__device__ __nv_bfloat16 g_xl [(size_t)MROWS_ * DIM_];   // x lo
__device__ __nv_bfloat16 g_wqkvh[(size_t)6144 * 2048];   // [Wq|Wk|Wv]^T hi  [n][k]
__device__ __nv_bfloat16 g_wqkvl[(size_t)6144 * 2048];
__device__ __nv_bfloat16 g_woh [(size_t)2048 * 2048];    // Wo^T hi [n][k]
__device__ __nv_bfloat16 g_wol [(size_t)2048 * 2048];
__device__ __nv_bfloat16 g_obh [(size_t)MROWS_ * DIM_];  // o_blend hi (b,n,h,v)
__device__ __nv_bfloat16 g_obl [(size_t)MROWS_ * DIM_];

// ===================== mma.sync (base-target PTX; fragments via plain LDS) ==
#define MMA16816(d, a, b0, b1) \
    asm volatile("mma.sync.aligned.m16n8k16.row.col.f32.bf16.bf16.f32 " \
        "{%0,%1,%2,%3}, {%4,%5,%6,%7}, {%8,%9}, {%0,%1,%2,%3};" \
        : "+f"((d)[0]), "+f"((d)[1]), "+f"((d)[2]), "+f"((d)[3]) \
        : "r"((a)[0]), "r"((a)[1]), "r"((a)[2]), "r"((a)[3]), "r"(b0), "r"(b1))

// ======================= bf16 split / transpose prep =======================
__global__ void k_split_x(const float* __restrict__ x) {
    size_t i = ((size_t)blockIdx.x * 256 + threadIdx.x) * 4;
    float4 v = *(const float4*)(x + i);
    float a[4] = {v.x, v.y, v.z, v.w};
    #pragma unroll
    for (int j = 0; j < 4; j++) {
        __nv_bfloat16 hi = __float2bfloat16_rn(a[j]);
        __nv_bfloat16 lo = __float2bfloat16_rn(a[j] - __bfloat162float(hi));
        g_xh[i + j] = hi; g_xl[i + j] = lo;
    }
}

__global__ void k_wsplit_qkv(const float* __restrict__ Wq, const float* __restrict__ Wk,
                             const float* __restrict__ Wv) {
    __shared__ float tile[32][33];
    int k0 = blockIdx.x * 32, n0 = blockIdx.y * 32;
    int which = n0 >> 11;
    const float* __restrict__ W = (which == 0) ? Wq : (which == 1 ? Wk : Wv);
    int nn0 = n0 & 2047;
    for (int r = threadIdx.y; r < 32; r += 8)
        tile[r][threadIdx.x] = W[(size_t)(k0 + r) * 2048 + nn0 + threadIdx.x];
    __syncthreads();
    for (int r = threadIdx.y; r < 32; r += 8) {
        float v = tile[threadIdx.x][r];
        __nv_bfloat16 hi = __float2bfloat16_rn(v);
        __nv_bfloat16 lo = __float2bfloat16_rn(v - __bfloat162float(hi));
        size_t o = (size_t)(n0 + r) * 2048 + k0 + threadIdx.x;
        g_wqkvh[o] = hi; g_wqkvl[o] = lo;
    }
}

__global__ void k_wsplit_o(const float* __restrict__ Wo) {
    __shared__ float tile[32][33];
    int k0 = blockIdx.x * 32, n0 = blockIdx.y * 32;
    for (int r = threadIdx.y; r < 32; r += 8)
        tile[r][threadIdx.x] = Wo[(size_t)(k0 + r) * 2048 + n0 + threadIdx.x];
    __syncthreads();
    for (int r = threadIdx.y; r < 32; r += 8) {
        float v = tile[threadIdx.x][r];
        __nv_bfloat16 hi = __float2bfloat16_rn(v);
        __nv_bfloat16 lo = __float2bfloat16_rn(v - __bfloat162float(hi));
        size_t o = (size_t)(n0 + r) * 2048 + k0 + threadIdx.x;
        g_woh[o] = hi; g_wol[o] = lo;
    }
}

// ======================= HMMA GEMM: C = A @ B^T (fp32 via bf16 3-pass split) ===
// Operand pointers selected INSIDE device code (device-global symbols are only
// valid device-side; host-passed they'd resolve to host shadows -> ATS zeros).
// mode 0: A=x split, B=Wqkv^T split, scatter to g_q/g_kf/g_v.
// mode 1: A=o_blend split, B=Wo^T split, write Cout row-major [m][2048].
__global__ __launch_bounds__(256)
void k_mma_gemm(float* __restrict__ Cout, int mode) {
    __shared__ __align__(16) __nv_bfloat16 sm[4][128][40];
    const __nv_bfloat16* __restrict__ Ah;
    const __nv_bfloat16* __restrict__ Al;
    const __nv_bfloat16* __restrict__ Bh;
    const __nv_bfloat16* __restrict__ Bl;
    if (mode == 0) { Ah = g_xh;  Al = g_xl;  Bh = g_wqkvh; Bl = g_wqkvl; }
    else           { Ah = g_obh; Al = g_obl; Bh = g_woh;   Bl = g_wol;   }

    const int tid = threadIdx.x;
    const int wid = tid >> 5, lane = tid & 31;
    const int wr = wid >> 1, wc = wid & 1;           // warp row 0..3, col 0..1
    const int m0 = blockIdx.x * 128;
    const int j0 = blockIdx.y * 128;
    const int gr = lane >> 2;                        // fragment row group 0..7
    const int gc = (lane & 3) * 2;                   // fragment col pair 0,2,4,6

    float acc[2][8][4];
    #pragma unroll
    for (int i = 0; i < 2; i++)
        #pragma unroll
        for (int j = 0; j < 8; j++)
            #pragma unroll
            for (int k = 0; k < 4; k++) acc[i][j][k] = 0.f;

    // global load indexing: 2048 uint4 per chunk (4 tiles x 128 rows x 4), 8/thread
    int gl_t[8], gl_row[8], gl_q[8];
    #pragma unroll
    for (int i = 0; i < 8; i++) {
        int idx = i * 256 + tid;
        gl_t[i] = idx >> 9;              // 0: Ah, 1: Al, 2: Bh, 3: Bl
        int rem = idx & 511;
        gl_row[i] = rem >> 2;
        gl_q[i] = rem & 3;               // 16B unit within 64B row-chunk
    }

    uint4 pf[8];
    auto ld_chunk = [&](int c) {
        #pragma unroll
        for (int i = 0; i < 8; i++) {
            const __nv_bfloat16* src =
                (gl_t[i] == 0) ? Ah : (gl_t[i] == 1) ? Al : (gl_t[i] == 2) ? Bh : Bl;
            int grow = (gl_t[i] < 2) ? (m0 + gl_row[i]) : (j0 + gl_row[i]);
            pf[i] = *(const uint4*)(src + (size_t)grow * 2048 + c * 32 + gl_q[i] * 8);
        }
    };

    ld_chunk(0);
    for (int c = 0; c < 64; c++) {
        __syncthreads();
        #pragma unroll
        for (int i = 0; i < 8; i++)
            *(uint4*)&sm[gl_t[i]][gl_row[i]][gl_q[i] * 8] = pf[i];
        __syncthreads();
        if (c < 63) ld_chunk(c + 1);

        #pragma unroll
        for (int s = 0; s < 2; s++) {
            const int kb = s * 16 + gc;
            uint32_t ahf[2][4], alf[2][4];
            #pragma unroll
            for (int i = 0; i < 2; i++) {
                int r0 = wr * 32 + i * 16 + gr;
                ahf[i][0] = *(const uint32_t*)&sm[0][r0    ][kb    ];
                ahf[i][1] = *(const uint32_t*)&sm[0][r0 + 8][kb    ];
                ahf[i][2] = *(const uint32_t*)&sm[0][r0    ][kb + 8];
                ahf[i][3] = *(const uint32_t*)&sm[0][r0 + 8][kb + 8];
                alf[i][0] = *(const uint32_t*)&sm[1][r0    ][kb    ];
                alf[i][1] = *(const uint32_t*)&sm[1][r0 + 8][kb    ];
                alf[i][2] = *(const uint32_t*)&sm[1][r0    ][kb + 8];
                alf[i][3] = *(const uint32_t*)&sm[1][r0 + 8][kb + 8];
            }
            #pragma unroll
            for (int t = 0; t < 8; t++) {
                int nr = wc * 64 + t * 8 + gr;
                uint32_t bh0 = *(const uint32_t*)&sm[2][nr][kb    ];
                uint32_t bh1 = *(const uint32_t*)&sm[2][nr][kb + 8];
                uint32_t bl0 = *(const uint32_t*)&sm[3][nr][kb    ];
                uint32_t bl1 = *(const uint32_t*)&sm[3][nr][kb + 8];
                #pragma unroll
                for (int i = 0; i < 2; i++) {
                    MMA16816(acc[i][t], ahf[i], bh0, bh1);
                    MMA16816(acc[i][t], ahf[i], bl0, bl1);
                    MMA16816(acc[i][t], alf[i], bh0, bh1);
                }
            }
        }
    }

    // epilogue (C fragment: c0,c1 at (gr, lane2), c2,c3 at (gr+8, lane2))
    const int lane2 = (lane & 3) * 2;
    if (mode == 0) {
        const int which = j0 >> 11;
        const int h = (j0 >> 7) & 15;
        const int b = m0 >> 12;
        float* slab = ((which == 0) ? g_q : (which == 1) ? g_kf : g_v)
                    + (size_t)(b * 16 + h) * 4096 * 128;
        #pragma unroll
        for (int i = 0; i < 2; i++) {
            int n = (m0 & 4095) + wr * 32 + i * 16 + gr;
            #pragma unroll
            for (int t = 0; t < 8; t++) {
                int col = wc * 64 + t * 8 + lane2;
                float* dst = slab + (size_t)n * 128 + col;
                *(float2*)dst = make_float2(acc[i][t][0], acc[i][t][1]);
                *(float2*)(dst + 8 * 128) = make_float2(acc[i][t][2], acc[i][t][3]);
            }
        }
    } else {
        #pragma unroll
        for (int i = 0; i < 2; i++) {
            int m = m0 + wr * 32 + i * 16 + gr;
            #pragma unroll
            for (int t = 0; t < 8; t++) {
                int col = j0 + wc * 64 + t * 8 + lane2;
                float* dst = Cout + (size_t)m * 2048 + col;
                *(float2*)dst = make_float2(acc[i][t][0], acc[i][t][1]);
                *(float2*)(dst + 8 * 2048) = make_float2(acc[i][t][2], acc[i][t][3]);
            }
        }
    }
}

// ======================= mean over N =======================
__global__ void k_meanpart(const float* __restrict__ x) {
    int gid = blockIdx.x * 256 + threadIdx.x;
    int sp = gid >> 13;
    int r  = gid & 8191;
    int b = r >> 11, d = r & 2047;
    float s = 0.f;
    int nbeg = sp * 512;
    #pragma unroll 4
    for (int n = nbeg; n < nbeg + 512; n++)
        s += x[(size_t)(b * N_ + n) * DIM_ + d];
    g_meanpart[gid] = s;
}

__global__ void k_meanred() {
    int r = blockIdx.x * 256 + threadIdx.x;
    float s = 0.f;
    #pragma unroll
    for (int sp = 0; sp < 8; sp++) s += g_meanpart[sp * 8192 + r];
    g_mean[r] = s * (1.f / 4096.f);
}

// ======================= gating MLP =======================
__global__ void k_mlp1(const float* __restrict__ f1_w, const float* __restrict__ f1_b) {
    __shared__ float xm[2048];
    int b = blockIdx.x;
    for (int i = threadIdx.x; i < 2048; i += 256) xm[i] = g_mean[b * 2048 + i];
    __syncthreads();
    int j = blockIdx.y * 256 + threadIdx.x;
    float s = 0.f;
    for (int k = 0; k < 2048; k++)
        s = fmaf(xm[k], f1_w[(size_t)k * 1024 + j], s);
    s += f1_b[j];
    g_h1[b * 1024 + j] = s / (1.f + expf(-s));
}

__global__ void k_mlp2(const float* __restrict__ f2_w, const float* __restrict__ f2_b,
                       float* __restrict__ dout) {
    __shared__ float red[128];
    int bh = blockIdx.x;
    int b = bh >> 4, h = bh & 15;
    float s = 0.f;
    for (int k = threadIdx.x; k < 1024; k += 128)
        s = fmaf(g_h1[b * 1024 + k], f2_w[k * 16 + h], s);
    red[threadIdx.x] = s; __syncthreads();
    for (int off = 64; off > 0; off >>= 1) {
        if (threadIdx.x < off) red[threadIdx.x] += red[threadIdx.x + off];
        __syncthreads();
    }
    if (threadIdx.x == 0) {
        float z = red[0] + f2_b[h];
        dout[OUT_OFF_PSI + bh] = 1.f / (1.f + expf(-z));
    }
}

// ======================= resonance + k_mod + decay split =======================
__global__ __launch_bounds__(256, 2)
void k_res(const float* __restrict__ Wb, const float* __restrict__ fast_slope,
           const float* __restrict__ slow_slope) {
    __shared__ float As[16][132];
    __shared__ float Bs[16][128];
    const int m0 = blockIdx.x * 128;
    const int bh = blockIdx.y;
    const int h = bh & 15;
    float* __restrict__ kslab = g_kf + (size_t)bh * N_ * DK_;
    float* __restrict__ kslow = g_ksl + (size_t)bh * N_ * DK_;
    const float* __restrict__ Wbh = Wb + (size_t)h * DK_ * DK_;
    const int tx = threadIdx.x, ty = threadIdx.y;
    const int tid = ty * 16 + tx;
    float acc[8][8];
    #pragma unroll
    for (int i = 0; i < 8; i++)
        #pragma unroll
        for (int j = 0; j < 8; j++) acc[i][j] = 0.f;

    const int arow = tid >> 2, acol = (tid & 3) * 4;
    const int brow = tid >> 5, bcol = (tid & 31) * 4;

    for (int kt = 0; kt < 128; kt += 16) {
        #pragma unroll
        for (int r = 0; r < 2; r++) {
            int row = arow + r * 64;
            float4 av = *(const float4*)&kslab[(size_t)(m0 + row) * DK_ + kt + acol];
            As[acol + 0][row] = av.x; As[acol + 1][row] = av.y;
            As[acol + 2][row] = av.z; As[acol + 3][row] = av.w;
        }
        #pragma unroll
        for (int r = 0; r < 2; r++) {
            int row = brow + r * 8;
            *(float4*)&Bs[row][bcol] =
                *(const float4*)&Wbh[(size_t)(kt + row) * DK_ + bcol];
        }
        __syncthreads();
        #pragma unroll
        for (int kk = 0; kk < 16; kk++) {
            float a[8], bb[8];
            *(float4*)&a[0]  = *(const float4*)&As[kk][ty * 8];
            *(float4*)&a[4]  = *(const float4*)&As[kk][ty * 8 + 4];
            *(float4*)&bb[0] = *(const float4*)&Bs[kk][tx * 8];
            *(float4*)&bb[4] = *(const float4*)&Bs[kk][tx * 8 + 4];
            #pragma unroll
            for (int i = 0; i < 8; i++)
                #pragma unroll
                for (int j = 0; j < 8; j++)
                    acc[i][j] = fmaf(a[i], bb[j], acc[i][j]);
        }
        __syncthreads();
    }
    const float fs = fast_slope[h], ss = slow_slope[h];
    #pragma unroll
    for (int i = 0; i < 8; i++) {
        int n = m0 + ty * 8 + i;
        float idx = (float)(n - (N_ - 1));
        float fw = expf(fs * idx);
        float sw = expf(ss * idx);
        #pragma unroll
        for (int j = 0; j < 8; j += 4) {
            size_t p = (size_t)n * DK_ + tx * 8 + j;
            float4 kr = *(const float4*)&kslab[p];
            float4 kf4, ks4;
            float r0, km;
            r0 = tanhf(acc[i][j+0]); km = kr.x * (1.f + 0.5f * r0) * INV_SQRT_DK; kf4.x = km * fw; ks4.x = km * sw;
            r0 = tanhf(acc[i][j+1]); km = kr.y * (1.f + 0.5f * r0) * INV_SQRT_DK; kf4.y = km * fw; ks4.y = km * sw;
            r0 = tanhf(acc[i][j+2]); km = kr.z * (1.f + 0.5f * r0) * INV_SQRT_DK; kf4.z = km * fw; ks4.z = km * sw;
            r0 = tanhf(acc[i][j+3]); km = kr.w * (1.f + 0.5f * r0) * INV_SQRT_DK; kf4.w = km * fw; ks4.w = km * sw;
            *(float4*)&kslab[p] = kf4;
            *(float4*)&kslow[p] = ks4;
        }
    }
}

// ======================= M = k^T @ v partials =======================
__global__ __launch_bounds__(256, 2)
void k_mpart() {
    __shared__ float As[16][128];
    __shared__ float Bs[16][128];
    const int split = blockIdx.x;
    const int bh = blockIdx.y;
    const int which = blockIdx.z;
    const float* __restrict__ kslab =
        (which ? g_ksl : g_kf) + (size_t)bh * N_ * DK_ + (size_t)split * 512 * DK_;
    const float* __restrict__ vslab =
        g_v + (size_t)bh * N_ * DK_ + (size_t)split * 512 * DK_;
    const int tx = threadIdx.x, ty = threadIdx.y;
    const int tid = ty * 16 + tx;
    float acc[8][8];
    #pragma unroll
    for (int i = 0; i < 8; i++)
        #pragma unroll
        for (int j = 0; j < 8; j++) acc[i][j] = 0.f;

    const int lrow = tid >> 5, lcol = (tid & 31) * 4;

    for (int nt = 0; nt < 512; nt += 16) {
        #pragma unroll
        for (int r = 0; r < 2; r++) {
            int row = lrow + r * 8;
            *(float4*)&As[row][lcol] = *(const float4*)&kslab[(size_t)(nt + row) * DK_ + lcol];
            *(float4*)&Bs[row][lcol] = *(const float4*)&vslab[(size_t)(nt + row) * DK_ + lcol];
        }
        __syncthreads();
        #pragma unroll
        for (int kk = 0; kk < 16; kk++) {
            float a[8], bb[8];
            *(float4*)&a[0]  = *(const float4*)&As[kk][ty * 8];
            *(float4*)&a[4]  = *(const float4*)&As[kk][ty * 8 + 4];
            *(float4*)&bb[0] = *(const float4*)&Bs[kk][tx * 8];
            *(float4*)&bb[4] = *(const float4*)&Bs[kk][tx * 8 + 4];
            #pragma unroll
            for (int i = 0; i < 8; i++)
                #pragma unroll
                for (int j = 0; j < 8; j++)
                    acc[i][j] = fmaf(a[i], bb[j], acc[i][j]);
        }
        __syncthreads();
    }
    float* dst = g_part + (((size_t)which * BH_ + bh) * 8 + split) * 16384;
    #pragma unroll
    for (int i = 0; i < 8; i++)
        #pragma unroll
        for (int j = 0; j < 8; j += 4) {
            float4 v4 = make_float4(acc[i][j], acc[i][j+1], acc[i][j+2], acc[i][j+3]);
            *(float4*)&dst[(ty * 8 + i) * 128 + tx * 8 + j] = v4;
        }
}

// ======================= M finalize =======================
__global__ void k_mfin(const float* __restrict__ Mf_prev, const float* __restrict__ Ms_prev,
                       const float* __restrict__ inter_fast, const float* __restrict__ inter_slow,
                       float* __restrict__ dout) {
    const int bh = blockIdx.x;
    const int which = blockIdx.y;
    const int h = bh & 15;
    const float inter = which ? inter_slow[h] : inter_fast[h];
    const float* prev = (which ? Ms_prev : Mf_prev) + (size_t)bh * 16384;
    const float* part = g_part + ((size_t)which * BH_ + bh) * 8 * 16384;
    float* dst = dout + (which ? OUT_OFF_MS : OUT_OFF_MF) + (size_t)bh * 16384;
    for (int e = threadIdx.x; e < 16384; e += 256) {
        float s = 0.f;
        #pragma unroll
        for (int sp = 0; sp < 8; sp++) s += part[(size_t)sp * 16384 + e];
        dst[e] = prev[e] * inter + s;
    }
}

// ======================= Mref = (I+S) @ M, blended =======================
__global__ __launch_bounds__(256, 2)
void k_mref(const float* __restrict__ S_fast, const float* __restrict__ S_slow,
            const float* __restrict__ dout, int which) {
    __shared__ float As[16][132];
    __shared__ float Bs[16][128];
    const int bh = blockIdx.x;
    const int h = bh & 15;
    const float* __restrict__ S = (which ? S_slow : S_fast) + (size_t)h * 16384;
    const float* __restrict__ M = dout + (which ? OUT_OFF_MS : OUT_OFF_MF) + (size_t)bh * 16384;
    const int tx = threadIdx.x, ty = threadIdx.y;
    const int tid = ty * 16 + tx;
    float acc[8][8];
    #pragma unroll
    for (int i = 0; i < 8; i++)
        #pragma unroll
        for (int j = 0; j < 8; j++) acc[i][j] = 0.f;

    const int arow = tid >> 2, acol = (tid & 3) * 4;
    const int brow = tid >> 5, bcol = (tid & 31) * 4;

    for (int kt = 0; kt < 128; kt += 16) {
        #pragma unroll
        for (int r = 0; r < 2; r++) {
            int row = arow + r * 64;
            float4 av = *(const float4*)&S[(size_t)row * 128 + kt + acol];
            As[acol + 0][row] = av.x + ((row == kt + acol + 0) ? 1.f : 0.f);
            As[acol + 1][row] = av.y + ((row == kt + acol + 1) ? 1.f : 0.f);
            As[acol + 2][row] = av.z + ((row == kt + acol + 2) ? 1.f : 0.f);
            As[acol + 3][row] = av.w + ((row == kt + acol + 3) ? 1.f : 0.f);
        }
        #pragma unroll
        for (int r = 0; r < 2; r++) {
            int row = brow + r * 8;
            *(float4*)&Bs[row][bcol] = *(const float4*)&M[(size_t)(kt + row) * 128 + bcol];
        }
        __syncthreads();
        #pragma unroll
        for (int kk = 0; kk < 16; kk++) {
            float a[8], bb[8];
            *(float4*)&a[0]  = *(const float4*)&As[kk][ty * 8];
            *(float4*)&a[4]  = *(const float4*)&As[kk][ty * 8 + 4];
            *(float4*)&bb[0] = *(const float4*)&Bs[kk][tx * 8];
            *(float4*)&bb[4] = *(const float4*)&Bs[kk][tx * 8 + 4];
            #pragma unroll
            for (int i = 0; i < 8; i++)
                #pragma unroll
                for (int j = 0; j < 8; j++)
                    acc[i][j] = fmaf(a[i], bb[j], acc[i][j]);
        }
        __syncthreads();
    }
    const float p = dout[OUT_OFF_PSI + bh];
    const float c0 = which ? p : (1.f - p);
    float* dst = g_mblend + (size_t)bh * 16384;
    #pragma unroll
    for (int i = 0; i < 8; i++)
        #pragma unroll
        for (int j = 0; j < 8; j++) {
            int idx = (ty * 8 + i) * 128 + tx * 8 + j;
            if (which == 0) dst[idx] = c0 * acc[i][j];
            else            dst[idx] += c0 * acc[i][j];
        }
}

// ======================= o_blend = q @ M_blend, bf16 split out =======================
__global__ __launch_bounds__(256, 2)
void k_oblend() {
    __shared__ float As[16][132];
    __shared__ float Bs[16][128];
    const int m0 = blockIdx.x * 128;
    const int bh = blockIdx.y;
    const float* __restrict__ qslab = g_q + (size_t)bh * N_ * DK_;
    const float* __restrict__ Mb = g_mblend + (size_t)bh * 16384;
    const int tx = threadIdx.x, ty = threadIdx.y;
    const int tid = ty * 16 + tx;
    float acc[8][8];
    #pragma unroll
    for (int i = 0; i < 8; i++)
        #pragma unroll
        for (int j = 0; j < 8; j++) acc[i][j] = 0.f;

    const int arow = tid >> 2, acol = (tid & 3) * 4;
    const int brow = tid >> 5, bcol = (tid & 31) * 4;

    for (int kt = 0; kt < 128; kt += 16) {
        #pragma unroll
        for (int r = 0; r < 2; r++) {
            int row = arow + r * 64;
            float4 av = *(const float4*)&qslab[(size_t)(m0 + row) * DK_ + kt + acol];
            As[acol + 0][row] = av.x; As[acol + 1][row] = av.y;
            As[acol + 2][row] = av.z; As[acol + 3][row] = av.w;
        }
        #pragma unroll
        for (int r = 0; r < 2; r++) {
            int row = brow + r * 8;
            *(float4*)&Bs[row][bcol] = *(const float4*)&Mb[(size_t)(kt + row) * 128 + bcol];
        }
        __syncthreads();
        #pragma unroll
        for (int kk = 0; kk < 16; kk++) {
            float a[8], bb[8];
            *(float4*)&a[0]  = *(const float4*)&As[kk][ty * 8];
            *(float4*)&a[4]  = *(const float4*)&As[kk][ty * 8 + 4];
            *(float4*)&bb[0] = *(const float4*)&Bs[kk][tx * 8];
            *(float4*)&bb[4] = *(const float4*)&Bs[kk][tx * 8 + 4];
            #pragma unroll
            for (int i = 0; i < 8; i++)
                #pragma unroll
                for (int j = 0; j < 8; j++)
                    acc[i][j] = fmaf(a[i], bb[j], acc[i][j]);
        }
        __syncthreads();
    }
    const int b = bh >> 4, h = bh & 15;
    #pragma unroll
    for (int i = 0; i < 8; i++) {
        int n = m0 + ty * 8 + i;
        size_t base = ((size_t)(b * N_ + n) * H_ + h) * DK_ + tx * 8;
        #pragma unroll
        for (int j = 0; j < 8; j++) {
            float v = acc[i][j];
            __nv_bfloat16 hi = __float2bfloat16_rn(v);
            __nv_bfloat16 lo = __float2bfloat16_rn(v - __bfloat162float(hi));
            g_obh[base + j] = hi; g_obl[base + j] = lo;
        }
    }
}

// ======================= launch =======================
extern "C" void kernel_launch(void* const* d_in, const int* in_sizes, int n_in,
                              void* d_out, int out_size) {
    (void)in_sizes; (void)n_in; (void)out_size;
    const float* x          = (const float*)d_in[0];
    const float* Mf_prev    = (const float*)d_in[1];
    const float* Ms_prev    = (const float*)d_in[2];
    const float* Wq         = (const float*)d_in[3];
    const float* Wk         = (const float*)d_in[4];
    const float* Wv         = (const float*)d_in[5];
    const float* Wo         = (const float*)d_in[6];
    const float* Wb         = (const float*)d_in[7];
    const float* fast_slope = (const float*)d_in[8];
    const float* slow_slope = (const float*)d_in[9];
    const float* inter_fast = (const float*)d_in[10];
    const float* inter_slow = (const float*)d_in[11];
    const float* S_fast     = (const float*)d_in[12];
    const float* S_slow     = (const float*)d_in[13];
    const float* f1_w       = (const float*)d_in[14];
    const float* f1_b       = (const float*)d_in[15];
    const float* f2_w       = (const float*)d_in[16];
    const float* f2_b       = (const float*)d_in[17];
    float* out = (float*)d_out;

    dim3 t16(16, 16);
    dim3 t328(32, 8);

    // prep: bf16 splits
    k_split_x<<<32768, 256>>>(x);
    k_wsplit_qkv<<<dim3(64, 192), t328>>>(Wq, Wk, Wv);
    k_wsplit_o<<<dim3(64, 64), t328>>>(Wo);

    // gating path
    k_meanpart<<<256, 256>>>(x);
    k_meanred<<<32, 256>>>();
    k_mlp1<<<dim3(4, 4), 256>>>(f1_w, f1_b);
    k_mlp2<<<64, 128>>>(f2_w, f2_b, out);

    // QKV projection (HMMA)
    k_mma_gemm<<<dim3(128, 48), 256>>>(nullptr, 0);

    // per-head path
    k_res<<<dim3(32, 64), t16>>>(Wb, fast_slope, slow_slope);
    k_mpart<<<dim3(8, 64, 2), t16>>>();
    k_mfin<<<dim3(64, 2), 256>>>(Mf_prev, Ms_prev, inter_fast, inter_slow, out);
    k_mref<<<64, t16>>>(S_fast, S_slow, out, 0);
    k_mref<<<64, t16>>>(S_fast, S_slow, out, 1);
    k_oblend<<<dim3(32, 64), t16>>>();

    // output projection (HMMA)
    k_mma_gemm<<<dim3(128, 16), 256>>>(out, 1);
}

// round 6
// speedup vs baseline: 2.0184x; 1.1758x over previous
#include <cuda_runtime.h>
#include <cuda_bf16.h>
#include <cstdint>
#include <math.h>

static constexpr int B_   = 4;
static constexpr int N_   = 4096;
static constexpr int H_   = 16;
static constexpr int DK_  = 128;
static constexpr int DIM_ = 2048;
static constexpr int BH_  = B_ * H_;      // 64
static constexpr int MROWS_ = B_ * N_;    // 16384
static constexpr float INV_SQRT_DK = 0.08838834764831843f;

static constexpr long long OUT_OFF_MF  = 33554432LL;
static constexpr long long OUT_OFF_MS  = 34603008LL;
static constexpr long long OUT_OFF_PSI = 35651584LL;

// ---------------- scratch (allocation-free: device globals) ----------------
__device__ float g_q  [(size_t)BH_ * N_ * DK_];   // (b,h,n,d) fp32
__device__ float g_kf [(size_t)BH_ * N_ * DK_];   // k raw -> k_fast in place
__device__ float g_ksl[(size_t)BH_ * N_ * DK_];   // k_slow
__device__ float g_v  [(size_t)BH_ * N_ * DK_];   // (b,h,n,v) fp32
__device__ float g_part[2LL * BH_ * 8 * DK_ * DK_];
__device__ float g_mblend[(size_t)BH_ * DK_ * DK_];
__device__ float g_meanpart[8 * B_ * DIM_];
__device__ float g_mean[B_ * DIM_];
__device__ float g_h1[B_ * 1024];

// bf16 split operands for HMMA GEMMs
__device__ __nv_bfloat16 g_xh [(size_t)MROWS_ * DIM_];   // x hi  [16384][2048]
__device__ __nv_bfloat16 g_xl [(size_t)MROWS_ * DIM_];   // x lo
__device__ __nv_bfloat16 g_wqkvh[(size_t)6144 * 2048];   // [Wq|Wk|Wv]^T hi  [n][k]
__device__ __nv_bfloat16 g_wqkvl[(size_t)6144 * 2048];
__device__ __nv_bfloat16 g_woh [(size_t)2048 * 2048];    // Wo^T hi [n][k]
__device__ __nv_bfloat16 g_wol [(size_t)2048 * 2048];
__device__ __nv_bfloat16 g_obh [(size_t)MROWS_ * DIM_];  // o_blend hi (b,n,h,v)
__device__ __nv_bfloat16 g_obl [(size_t)MROWS_ * DIM_];

// ===================== mma.sync helpers (base-target PTX) ==================
__device__ __forceinline__ uint32_t smem_u32(const void* p) {
    uint32_t a;
    asm("{ .reg .u64 t; cvta.to.shared.u64 t, %1; cvt.u32.u64 %0, t; }"
        : "=r"(a) : "l"(p));
    return a;
}

#define MMA16816(d, a, b0, b1) \
    asm volatile("mma.sync.aligned.m16n8k16.row.col.f32.bf16.bf16.f32 " \
        "{%0,%1,%2,%3}, {%4,%5,%6,%7}, {%8,%9}, {%0,%1,%2,%3};" \
        : "+f"((d)[0]), "+f"((d)[1]), "+f"((d)[2]), "+f"((d)[3]) \
        : "r"((a)[0]), "r"((a)[1]), "r"((a)[2]), "r"((a)[3]), "r"(b0), "r"(b1))

#define LDSM_X4(r, addr) \
    asm volatile("ldmatrix.sync.aligned.m8n8.x4.shared.b16 {%0,%1,%2,%3}, [%4];" \
        : "=r"((r)[0]), "=r"((r)[1]), "=r"((r)[2]), "=r"((r)[3]) : "r"(addr))

#define CP_ASYNC16(dst, src) \
    asm volatile("cp.async.cg.shared.global [%0], [%1], 16;" \
        :: "r"(dst), "l"(src) : "memory")
#define CP_COMMIT() asm volatile("cp.async.commit_group;" ::: "memory")
#define CP_WAIT(n)  asm volatile("cp.async.wait_group %0;" :: "n"(n) : "memory")

// ======================= bf16 split / transpose prep =======================
__global__ void k_split_x(const float* __restrict__ x) {
    size_t i = ((size_t)blockIdx.x * 256 + threadIdx.x) * 4;
    float4 v = *(const float4*)(x + i);
    float a[4] = {v.x, v.y, v.z, v.w};
    #pragma unroll
    for (int j = 0; j < 4; j++) {
        __nv_bfloat16 hi = __float2bfloat16_rn(a[j]);
        __nv_bfloat16 lo = __float2bfloat16_rn(a[j] - __bfloat162float(hi));
        g_xh[i + j] = hi; g_xl[i + j] = lo;
    }
}

__global__ void k_wsplit_qkv(const float* __restrict__ Wq, const float* __restrict__ Wk,
                             const float* __restrict__ Wv) {
    __shared__ float tile[32][33];
    int k0 = blockIdx.x * 32, n0 = blockIdx.y * 32;
    int which = n0 >> 11;
    const float* __restrict__ W = (which == 0) ? Wq : (which == 1 ? Wk : Wv);
    int nn0 = n0 & 2047;
    for (int r = threadIdx.y; r < 32; r += 8)
        tile[r][threadIdx.x] = W[(size_t)(k0 + r) * 2048 + nn0 + threadIdx.x];
    __syncthreads();
    for (int r = threadIdx.y; r < 32; r += 8) {
        float v = tile[threadIdx.x][r];
        __nv_bfloat16 hi = __float2bfloat16_rn(v);
        __nv_bfloat16 lo = __float2bfloat16_rn(v - __bfloat162float(hi));
        size_t o = (size_t)(n0 + r) * 2048 + k0 + threadIdx.x;
        g_wqkvh[o] = hi; g_wqkvl[o] = lo;
    }
}

__global__ void k_wsplit_o(const float* __restrict__ Wo) {
    __shared__ float tile[32][33];
    int k0 = blockIdx.x * 32, n0 = blockIdx.y * 32;
    for (int r = threadIdx.y; r < 32; r += 8)
        tile[r][threadIdx.x] = Wo[(size_t)(k0 + r) * 2048 + n0 + threadIdx.x];
    __syncthreads();
    for (int r = threadIdx.y; r < 32; r += 8) {
        float v = tile[threadIdx.x][r];
        __nv_bfloat16 hi = __float2bfloat16_rn(v);
        __nv_bfloat16 lo = __float2bfloat16_rn(v - __bfloat162float(hi));
        size_t o = (size_t)(n0 + r) * 2048 + k0 + threadIdx.x;
        g_woh[o] = hi; g_wol[o] = lo;
    }
}

// ======================= HMMA GEMM: C = A @ B^T (fp32 via bf16 3-pass split) ===
// Device-side operand selection (device-global symbols host-side are shadows).
// Grid: blockIdx.x = j-block (N), blockIdx.y = m-block (M) -> waves cover all
// j for few m; A reused from L2 across j.
// 2-stage cp.async pipeline; ldmatrix.x4 fragments; smem row stride 40 elems
// (80B -> conflict-free ldmatrix).
static constexpr int SSTG = 4 * 128 * 40;            // elems per stage

__global__ __launch_bounds__(256)
void k_mma_gemm(float* __restrict__ Cout, int mode) {
    extern __shared__ __align__(16) __nv_bfloat16 smb[];   // 2 * SSTG elems
    const __nv_bfloat16* __restrict__ Ah;
    const __nv_bfloat16* __restrict__ Al;
    const __nv_bfloat16* __restrict__ Bh;
    const __nv_bfloat16* __restrict__ Bl;
    if (mode == 0) { Ah = g_xh;  Al = g_xl;  Bh = g_wqkvh; Bl = g_wqkvl; }
    else           { Ah = g_obh; Al = g_obl; Bh = g_woh;   Bl = g_wol;   }

    const uint32_t sbase = smem_u32(smb);
    const int tid = threadIdx.x;
    const int wid = tid >> 5, lane = tid & 31;
    const int wr = wid >> 1, wc = wid & 1;           // warp row 0..3, col 0..1
    const int j0 = blockIdx.x * 128;
    const int m0 = blockIdx.y * 128;
    const int l15 = lane & 15;
    const int lhalf = (lane >> 4) * 8;               // k-half select for ldmatrix

    float acc[2][8][4];
    #pragma unroll
    for (int i = 0; i < 2; i++)
        #pragma unroll
        for (int j = 0; j < 8; j++)
            #pragma unroll
            for (int k = 0; k < 4; k++) acc[i][j][k] = 0.f;

    // global->smem: 2048 16B segments per chunk, 8 per thread
    int gl_t[8], gl_row[8], gl_q[8];
    const __nv_bfloat16* gl_src[8];
    #pragma unroll
    for (int i = 0; i < 8; i++) {
        int idx = i * 256 + tid;
        gl_t[i] = idx >> 9;              // 0: Ah, 1: Al, 2: Bh, 3: Bl
        int rem = idx & 511;
        gl_row[i] = rem >> 2;
        gl_q[i] = rem & 3;
        gl_src[i] = (gl_t[i] == 0) ? Ah : (gl_t[i] == 1) ? Al
                  : (gl_t[i] == 2) ? Bh : Bl;
    }

    auto issue = [&](int c, int st) {
        #pragma unroll
        for (int i = 0; i < 8; i++) {
            int grow = (gl_t[i] < 2) ? (m0 + gl_row[i]) : (j0 + gl_row[i]);
            const __nv_bfloat16* src = gl_src[i] + (size_t)grow * 2048 + c * 32 + gl_q[i] * 8;
            uint32_t dst = sbase +
                (uint32_t)(st * SSTG + gl_t[i] * 5120 + gl_row[i] * 40 + gl_q[i] * 8) * 2;
            CP_ASYNC16(dst, src);
        }
        CP_COMMIT();
    };

    issue(0, 0);
    for (int c = 0; c < 64; c++) {
        if (c < 63) { issue(c + 1, (c + 1) & 1); CP_WAIT(1); }
        else        { CP_WAIT(0); }
        __syncthreads();
        const uint32_t stg = sbase + (uint32_t)((c & 1) * SSTG) * 2;

        #pragma unroll
        for (int s = 0; s < 2; s++) {
            const uint32_t kcol = (uint32_t)(s * 16 + lhalf) * 2;   // bytes
            uint32_t ah[2][4], al[2][4], bhf[4][4], blf[4][4];
            #pragma unroll
            for (int i = 0; i < 2; i++) {
                uint32_t ar = stg + (uint32_t)((wr * 32 + i * 16 + l15) * 40) * 2 + kcol;
                LDSM_X4(ah[i], ar);                          // tile 0 (Ah)
                LDSM_X4(al[i], ar + (uint32_t)5120 * 2);     // tile 1 (Al)
            }
            #pragma unroll
            for (int p = 0; p < 4; p++) {
                uint32_t br = stg + (uint32_t)(2 * 5120 + (wc * 64 + p * 16 + l15) * 40) * 2 + kcol;
                LDSM_X4(bhf[p], br);                         // tile 2 (Bh)
                LDSM_X4(blf[p], br + (uint32_t)5120 * 2);    // tile 3 (Bl)
            }
            #pragma unroll
            for (int i = 0; i < 2; i++)
                #pragma unroll
                for (int t = 0; t < 8; t++) {
                    const int p = t >> 1, sel = t & 1;
                    MMA16816(acc[i][t], ah[i], bhf[p][sel], bhf[p][sel + 2]);
                    MMA16816(acc[i][t], ah[i], blf[p][sel], blf[p][sel + 2]);
                    MMA16816(acc[i][t], al[i], bhf[p][sel], bhf[p][sel + 2]);
                }
        }
        __syncthreads();
    }

    // epilogue (C fragment: c0,c1 at (gr, lane2), c2,c3 at (gr+8, lane2))
    const int gr = lane >> 2;
    const int lane2 = (lane & 3) * 2;
    if (mode == 0) {
        const int which = j0 >> 11;
        const int h = (j0 >> 7) & 15;
        const int b = m0 >> 12;
        float* slab = ((which == 0) ? g_q : (which == 1) ? g_kf : g_v)
                    + (size_t)(b * 16 + h) * 4096 * 128;
        #pragma unroll
        for (int i = 0; i < 2; i++) {
            int n = (m0 & 4095) + wr * 32 + i * 16 + gr;
            #pragma unroll
            for (int t = 0; t < 8; t++) {
                int col = wc * 64 + t * 8 + lane2;
                float* dst = slab + (size_t)n * 128 + col;
                *(float2*)dst = make_float2(acc[i][t][0], acc[i][t][1]);
                *(float2*)(dst + 8 * 128) = make_float2(acc[i][t][2], acc[i][t][3]);
            }
        }
    } else {
        #pragma unroll
        for (int i = 0; i < 2; i++) {
            int m = m0 + wr * 32 + i * 16 + gr;
            #pragma unroll
            for (int t = 0; t < 8; t++) {
                int col = j0 + wc * 64 + t * 8 + lane2;
                float* dst = Cout + (size_t)m * 2048 + col;
                *(float2*)dst = make_float2(acc[i][t][0], acc[i][t][1]);
                *(float2*)(dst + 8 * 2048) = make_float2(acc[i][t][2], acc[i][t][3]);
            }
        }
    }
}

// ======================= mean over N =======================
__global__ void k_meanpart(const float* __restrict__ x) {
    int gid = blockIdx.x * 256 + threadIdx.x;
    int sp = gid >> 13;
    int r  = gid & 8191;
    int b = r >> 11, d = r & 2047;
    float s = 0.f;
    int nbeg = sp * 512;
    #pragma unroll 4
    for (int n = nbeg; n < nbeg + 512; n++)
        s += x[(size_t)(b * N_ + n) * DIM_ + d];
    g_meanpart[gid] = s;
}

__global__ void k_meanred() {
    int r = blockIdx.x * 256 + threadIdx.x;
    float s = 0.f;
    #pragma unroll
    for (int sp = 0; sp < 8; sp++) s += g_meanpart[sp * 8192 + r];
    g_mean[r] = s * (1.f / 4096.f);
}

// ======================= gating MLP =======================
__global__ void k_mlp1(const float* __restrict__ f1_w, const float* __restrict__ f1_b) {
    __shared__ float xm[2048];
    int b = blockIdx.x;
    for (int i = threadIdx.x; i < 2048; i += 256) xm[i] = g_mean[b * 2048 + i];
    __syncthreads();
    int j = blockIdx.y * 256 + threadIdx.x;
    float s = 0.f;
    for (int k = 0; k < 2048; k++)
        s = fmaf(xm[k], f1_w[(size_t)k * 1024 + j], s);
    s += f1_b[j];
    g_h1[b * 1024 + j] = s / (1.f + expf(-s));
}

__global__ void k_mlp2(const float* __restrict__ f2_w, const float* __restrict__ f2_b,
                       float* __restrict__ dout) {
    __shared__ float red[128];
    int bh = blockIdx.x;
    int b = bh >> 4, h = bh & 15;
    float s = 0.f;
    for (int k = threadIdx.x; k < 1024; k += 128)
        s = fmaf(g_h1[b * 1024 + k], f2_w[k * 16 + h], s);
    red[threadIdx.x] = s; __syncthreads();
    for (int off = 64; off > 0; off >>= 1) {
        if (threadIdx.x < off) red[threadIdx.x] += red[threadIdx.x + off];
        __syncthreads();
    }
    if (threadIdx.x == 0) {
        float z = red[0] + f2_b[h];
        dout[OUT_OFF_PSI + bh] = 1.f / (1.f + expf(-z));
    }
}

// ======================= resonance + k_mod + decay split =======================
__global__ __launch_bounds__(256, 2)
void k_res(const float* __restrict__ Wb, const float* __restrict__ fast_slope,
           const float* __restrict__ slow_slope) {
    __shared__ float As[16][132];
    __shared__ float Bs[16][128];
    const int m0 = blockIdx.x * 128;
    const int bh = blockIdx.y;
    const int h = bh & 15;
    float* __restrict__ kslab = g_kf + (size_t)bh * N_ * DK_;
    float* __restrict__ kslow = g_ksl + (size_t)bh * N_ * DK_;
    const float* __restrict__ Wbh = Wb + (size_t)h * DK_ * DK_;
    const int tx = threadIdx.x, ty = threadIdx.y;
    const int tid = ty * 16 + tx;
    float acc[8][8];
    #pragma unroll
    for (int i = 0; i < 8; i++)
        #pragma unroll
        for (int j = 0; j < 8; j++) acc[i][j] = 0.f;

    const int arow = tid >> 2, acol = (tid & 3) * 4;
    const int brow = tid >> 5, bcol = (tid & 31) * 4;

    for (int kt = 0; kt < 128; kt += 16) {
        #pragma unroll
        for (int r = 0; r < 2; r++) {
            int row = arow + r * 64;
            float4 av = *(const float4*)&kslab[(size_t)(m0 + row) * DK_ + kt + acol];
            As[acol + 0][row] = av.x; As[acol + 1][row] = av.y;
            As[acol + 2][row] = av.z; As[acol + 3][row] = av.w;
        }
        #pragma unroll
        for (int r = 0; r < 2; r++) {
            int row = brow + r * 8;
            *(float4*)&Bs[row][bcol] =
                *(const float4*)&Wbh[(size_t)(kt + row) * DK_ + bcol];
        }
        __syncthreads();
        #pragma unroll
        for (int kk = 0; kk < 16; kk++) {
            float a[8], bb[8];
            *(float4*)&a[0]  = *(const float4*)&As[kk][ty * 8];
            *(float4*)&a[4]  = *(const float4*)&As[kk][ty * 8 + 4];
            *(float4*)&bb[0] = *(const float4*)&Bs[kk][tx * 8];
            *(float4*)&bb[4] = *(const float4*)&Bs[kk][tx * 8 + 4];
            #pragma unroll
            for (int i = 0; i < 8; i++)
                #pragma unroll
                for (int j = 0; j < 8; j++)
                    acc[i][j] = fmaf(a[i], bb[j], acc[i][j]);
        }
        __syncthreads();
    }
    const float fs = fast_slope[h], ss = slow_slope[h];
    #pragma unroll
    for (int i = 0; i < 8; i++) {
        int n = m0 + ty * 8 + i;
        float idx = (float)(n - (N_ - 1));
        float fw = expf(fs * idx);
        float sw = expf(ss * idx);
        #pragma unroll
        for (int j = 0; j < 8; j += 4) {
            size_t p = (size_t)n * DK_ + tx * 8 + j;
            float4 kr = *(const float4*)&kslab[p];
            float4 kf4, ks4;
            float r0, km;
            r0 = tanhf(acc[i][j+0]); km = kr.x * (1.f + 0.5f * r0) * INV_SQRT_DK; kf4.x = km * fw; ks4.x = km * sw;
            r0 = tanhf(acc[i][j+1]); km = kr.y * (1.f + 0.5f * r0) * INV_SQRT_DK; kf4.y = km * fw; ks4.y = km * sw;
            r0 = tanhf(acc[i][j+2]); km = kr.z * (1.f + 0.5f * r0) * INV_SQRT_DK; kf4.z = km * fw; ks4.z = km * sw;
            r0 = tanhf(acc[i][j+3]); km = kr.w * (1.f + 0.5f * r0) * INV_SQRT_DK; kf4.w = km * fw; ks4.w = km * sw;
            *(float4*)&kslab[p] = kf4;
            *(float4*)&kslow[p] = ks4;
        }
    }
}

// ======================= M = k^T @ v partials =======================
__global__ __launch_bounds__(256, 2)
void k_mpart() {
    __shared__ float As[16][128];
    __shared__ float Bs[16][128];
    const int split = blockIdx.x;
    const int bh = blockIdx.y;
    const int which = blockIdx.z;
    const float* __restrict__ kslab =
        (which ? g_ksl : g_kf) + (size_t)bh * N_ * DK_ + (size_t)split * 512 * DK_;
    const float* __restrict__ vslab =
        g_v + (size_t)bh * N_ * DK_ + (size_t)split * 512 * DK_;
    const int tx = threadIdx.x, ty = threadIdx.y;
    const int tid = ty * 16 + tx;
    float acc[8][8];
    #pragma unroll
    for (int i = 0; i < 8; i++)
        #pragma unroll
        for (int j = 0; j < 8; j++) acc[i][j] = 0.f;

    const int lrow = tid >> 5, lcol = (tid & 31) * 4;

    for (int nt = 0; nt < 512; nt += 16) {
        #pragma unroll
        for (int r = 0; r < 2; r++) {
            int row = lrow + r * 8;
            *(float4*)&As[row][lcol] = *(const float4*)&kslab[(size_t)(nt + row) * DK_ + lcol];
            *(float4*)&Bs[row][lcol] = *(const float4*)&vslab[(size_t)(nt + row) * DK_ + lcol];
        }
        __syncthreads();
        #pragma unroll
        for (int kk = 0; kk < 16; kk++) {
            float a[8], bb[8];
            *(float4*)&a[0]  = *(const float4*)&As[kk][ty * 8];
            *(float4*)&a[4]  = *(const float4*)&As[kk][ty * 8 + 4];
            *(float4*)&bb[0] = *(const float4*)&Bs[kk][tx * 8];
            *(float4*)&bb[4] = *(const float4*)&Bs[kk][tx * 8 + 4];
            #pragma unroll
            for (int i = 0; i < 8; i++)
                #pragma unroll
                for (int j = 0; j < 8; j++)
                    acc[i][j] = fmaf(a[i], bb[j], acc[i][j]);
        }
        __syncthreads();
    }
    float* dst = g_part + (((size_t)which * BH_ + bh) * 8 + split) * 16384;
    #pragma unroll
    for (int i = 0; i < 8; i++)
        #pragma unroll
        for (int j = 0; j < 8; j += 4) {
            float4 v4 = make_float4(acc[i][j], acc[i][j+1], acc[i][j+2], acc[i][j+3]);
            *(float4*)&dst[(ty * 8 + i) * 128 + tx * 8 + j] = v4;
        }
}

// ======================= M finalize =======================
__global__ void k_mfin(const float* __restrict__ Mf_prev, const float* __restrict__ Ms_prev,
                       const float* __restrict__ inter_fast, const float* __restrict__ inter_slow,
                       float* __restrict__ dout) {
    const int bh = blockIdx.x;
    const int which = blockIdx.y;
    const int h = bh & 15;
    const float inter = which ? inter_slow[h] : inter_fast[h];
    const float* prev = (which ? Ms_prev : Mf_prev) + (size_t)bh * 16384;
    const float* part = g_part + ((size_t)which * BH_ + bh) * 8 * 16384;
    float* dst = dout + (which ? OUT_OFF_MS : OUT_OFF_MF) + (size_t)bh * 16384;
    for (int e = threadIdx.x; e < 16384; e += 256) {
        float s = 0.f;
        #pragma unroll
        for (int sp = 0; sp < 8; sp++) s += part[(size_t)sp * 16384 + e];
        dst[e] = prev[e] * inter + s;
    }
}

// ======================= Mref = (I+S) @ M, blended =======================
__global__ __launch_bounds__(256, 2)
void k_mref(const float* __restrict__ S_fast, const float* __restrict__ S_slow,
            const float* __restrict__ dout, int which) {
    __shared__ float As[16][132];
    __shared__ float Bs[16][128];
    const int bh = blockIdx.x;
    const int h = bh & 15;
    const float* __restrict__ S = (which ? S_slow : S_fast) + (size_t)h * 16384;
    const float* __restrict__ M = dout + (which ? OUT_OFF_MS : OUT_OFF_MF) + (size_t)bh * 16384;
    const int tx = threadIdx.x, ty = threadIdx.y;
    const int tid = ty * 16 + tx;
    float acc[8][8];
    #pragma unroll
    for (int i = 0; i < 8; i++)
        #pragma unroll
        for (int j = 0; j < 8; j++) acc[i][j] = 0.f;

    const int arow = tid >> 2, acol = (tid & 3) * 4;
    const int brow = tid >> 5, bcol = (tid & 31) * 4;

    for (int kt = 0; kt < 128; kt += 16) {
        #pragma unroll
        for (int r = 0; r < 2; r++) {
            int row = arow + r * 64;
            float4 av = *(const float4*)&S[(size_t)row * 128 + kt + acol];
            As[acol + 0][row] = av.x + ((row == kt + acol + 0) ? 1.f : 0.f);
            As[acol + 1][row] = av.y + ((row == kt + acol + 1) ? 1.f : 0.f);
            As[acol + 2][row] = av.z + ((row == kt + acol + 2) ? 1.f : 0.f);
            As[acol + 3][row] = av.w + ((row == kt + acol + 3) ? 1.f : 0.f);
        }
        #pragma unroll
        for (int r = 0; r < 2; r++) {
            int row = brow + r * 8;
            *(float4*)&Bs[row][bcol] = *(const float4*)&M[(size_t)(kt + row) * 128 + bcol];
        }
        __syncthreads();
        #pragma unroll
        for (int kk = 0; kk < 16; kk++) {
            float a[8], bb[8];
            *(float4*)&a[0]  = *(const float4*)&As[kk][ty * 8];
            *(float4*)&a[4]  = *(const float4*)&As[kk][ty * 8 + 4];
            *(float4*)&bb[0] = *(const float4*)&Bs[kk][tx * 8];
            *(float4*)&bb[4] = *(const float4*)&Bs[kk][tx * 8 + 4];
            #pragma unroll
            for (int i = 0; i < 8; i++)
                #pragma unroll
                for (int j = 0; j < 8; j++)
                    acc[i][j] = fmaf(a[i], bb[j], acc[i][j]);
        }
        __syncthreads();
    }
    const float p = dout[OUT_OFF_PSI + bh];
    const float c0 = which ? p : (1.f - p);
    float* dst = g_mblend + (size_t)bh * 16384;
    #pragma unroll
    for (int i = 0; i < 8; i++)
        #pragma unroll
        for (int j = 0; j < 8; j++) {
            int idx = (ty * 8 + i) * 128 + tx * 8 + j;
            if (which == 0) dst[idx] = c0 * acc[i][j];
            else            dst[idx] += c0 * acc[i][j];
        }
}

// ======================= o_blend = q @ M_blend, bf16 split out =======================
__global__ __launch_bounds__(256, 2)
void k_oblend() {
    __shared__ float As[16][132];
    __shared__ float Bs[16][128];
    const int m0 = blockIdx.x * 128;
    const int bh = blockIdx.y;
    const float* __restrict__ qslab = g_q + (size_t)bh * N_ * DK_;
    const float* __restrict__ Mb = g_mblend + (size_t)bh * 16384;
    const int tx = threadIdx.x, ty = threadIdx.y;
    const int tid = ty * 16 + tx;
    float acc[8][8];
    #pragma unroll
    for (int i = 0; i < 8; i++)
        #pragma unroll
        for (int j = 0; j < 8; j++) acc[i][j] = 0.f;

    const int arow = tid >> 2, acol = (tid & 3) * 4;
    const int brow = tid >> 5, bcol = (tid & 31) * 4;

    for (int kt = 0; kt < 128; kt += 16) {
        #pragma unroll
        for (int r = 0; r < 2; r++) {
            int row = arow + r * 64;
            float4 av = *(const float4*)&qslab[(size_t)(m0 + row) * DK_ + kt + acol];
            As[acol + 0][row] = av.x; As[acol + 1][row] = av.y;
            As[acol + 2][row] = av.z; As[acol + 3][row] = av.w;
        }
        #pragma unroll
        for (int r = 0; r < 2; r++) {
            int row = brow + r * 8;
            *(float4*)&Bs[row][bcol] = *(const float4*)&Mb[(size_t)(kt + row) * 128 + bcol];
        }
        __syncthreads();
        #pragma unroll
        for (int kk = 0; kk < 16; kk++) {
            float a[8], bb[8];
            *(float4*)&a[0]  = *(const float4*)&As[kk][ty * 8];
            *(float4*)&a[4]  = *(const float4*)&As[kk][ty * 8 + 4];
            *(float4*)&bb[0] = *(const float4*)&Bs[kk][tx * 8];
            *(float4*)&bb[4] = *(const float4*)&Bs[kk][tx * 8 + 4];
            #pragma unroll
            for (int i = 0; i < 8; i++)
                #pragma unroll
                for (int j = 0; j < 8; j++)
                    acc[i][j] = fmaf(a[i], bb[j], acc[i][j]);
        }
        __syncthreads();
    }
    const int b = bh >> 4, h = bh & 15;
    #pragma unroll
    for (int i = 0; i < 8; i++) {
        int n = m0 + ty * 8 + i;
        size_t base = ((size_t)(b * N_ + n) * H_ + h) * DK_ + tx * 8;
        #pragma unroll
        for (int j = 0; j < 8; j++) {
            float v = acc[i][j];
            __nv_bfloat16 hi = __float2bfloat16_rn(v);
            __nv_bfloat16 lo = __float2bfloat16_rn(v - __bfloat162float(hi));
            g_obh[base + j] = hi; g_obl[base + j] = lo;
        }
    }
}

// ======================= launch =======================
extern "C" void kernel_launch(void* const* d_in, const int* in_sizes, int n_in,
                              void* d_out, int out_size) {
    (void)in_sizes; (void)n_in; (void)out_size;
    const float* x          = (const float*)d_in[0];
    const float* Mf_prev    = (const float*)d_in[1];
    const float* Ms_prev    = (const float*)d_in[2];
    const float* Wq         = (const float*)d_in[3];
    const float* Wk         = (const float*)d_in[4];
    const float* Wv         = (const float*)d_in[5];
    const float* Wo         = (const float*)d_in[6];
    const float* Wb         = (const float*)d_in[7];
    const float* fast_slope = (const float*)d_in[8];
    const float* slow_slope = (const float*)d_in[9];
    const float* inter_fast = (const float*)d_in[10];
    const float* inter_slow = (const float*)d_in[11];
    const float* S_fast     = (const float*)d_in[12];
    const float* S_slow     = (const float*)d_in[13];
    const float* f1_w       = (const float*)d_in[14];
    const float* f1_b       = (const float*)d_in[15];
    const float* f2_w       = (const float*)d_in[16];
    const float* f2_b       = (const float*)d_in[17];
    float* out = (float*)d_out;

    const int gemm_smem = 2 * SSTG * 2;   // 81920 bytes
    static bool attr_set = false;
    if (!attr_set) {
        cudaFuncSetAttribute(k_mma_gemm, cudaFuncAttributeMaxDynamicSharedMemorySize, gemm_smem);
        attr_set = true;
    }

    dim3 t16(16, 16);
    dim3 t328(32, 8);

    // prep: bf16 splits
    k_split_x<<<32768, 256>>>(x);
    k_wsplit_qkv<<<dim3(64, 192), t328>>>(Wq, Wk, Wv);
    k_wsplit_o<<<dim3(64, 64), t328>>>(Wo);

    // gating path
    k_meanpart<<<256, 256>>>(x);
    k_meanred<<<32, 256>>>();
    k_mlp1<<<dim3(4, 4), 256>>>(f1_w, f1_b);
    k_mlp2<<<64, 128>>>(f2_w, f2_b, out);

    // QKV projection (HMMA, grid: x=j-blocks, y=m-blocks)
    k_mma_gemm<<<dim3(48, 128), 256, gemm_smem>>>(nullptr, 0);

    // per-head path
    k_res<<<dim3(32, 64), t16>>>(Wb, fast_slope, slow_slope);
    k_mpart<<<dim3(8, 64, 2), t16>>>();
    k_mfin<<<dim3(64, 2), 256>>>(Mf_prev, Ms_prev, inter_fast, inter_slow, out);
    k_mref<<<64, t16>>>(S_fast, S_slow, out, 0);
    k_mref<<<64, t16>>>(S_fast, S_slow, out, 1);
    k_oblend<<<dim3(32, 64), t16>>>();

    // output projection (HMMA)
    k_mma_gemm<<<dim3(16, 128), 256, gemm_smem>>>(out, 1);
}